// round 4
// baseline (speedup 1.0000x reference)
#include <cuda_runtime.h>
#include <math.h>

// ---------------------------------------------------------------------------
// Static device scratch (no allocations allowed)
// ---------------------------------------------------------------------------
__device__ float g_x0[256 * 64 * 64];     // x after double inorm        (4 MB)
__device__ float g_g2[256 * 128 * 128];   // guide lv2                   (16 MB)
__device__ float g_kk16[128 * 128 * 4];   // kk map for pac16
__device__ float g_x1[128 * 128 * 128];   // pac16 out / inorm in-place  (8 MB)
__device__ float g_g1[128 * 256 * 256];   // guide lv1                   (32 MB)
__device__ float g_kk20[256 * 256 * 4];   // kk map for pac20
__device__ float g_x2[64 * 256 * 256];    // pac20 out / inorm in-place  (16 MB)

// ---------------------------------------------------------------------------
// Fused double (instance-norm + residual):
//   y = inorm(x)+x applied twice == scale*x + shift with
//   r1 = rsqrt(v+eps), a = 1+r1, r2 = rsqrt(a*a*v+eps)
//   scale = a*(r2+1), shift = -(a*r2 + r1)*m
// ---------------------------------------------------------------------------
__global__ void inorm2_kernel(const float* x, float* y, int HW) {
    int c = blockIdx.x;
    const float* xc = x + (size_t)c * HW;
    float* yc = y + (size_t)c * HW;

    float s = 0.f, s2 = 0.f;
    for (int i = threadIdx.x; i < HW; i += blockDim.x) {
        float v = xc[i];
        s += v;
        s2 = fmaf(v, v, s2);
    }
    __shared__ float rs[32], rs2[32];
    #pragma unroll
    for (int o = 16; o; o >>= 1) {
        s += __shfl_xor_sync(0xFFFFFFFFu, s, o);
        s2 += __shfl_xor_sync(0xFFFFFFFFu, s2, o);
    }
    int w = threadIdx.x >> 5, l = threadIdx.x & 31;
    if (l == 0) { rs[w] = s; rs2[w] = s2; }
    __syncthreads();
    int nw = blockDim.x >> 5;
    if (w == 0) {
        s = (l < nw) ? rs[l] : 0.f;
        s2 = (l < nw) ? rs2[l] : 0.f;
        #pragma unroll
        for (int o = 16; o; o >>= 1) {
            s += __shfl_xor_sync(0xFFFFFFFFu, s, o);
            s2 += __shfl_xor_sync(0xFFFFFFFFu, s2, o);
        }
        if (l == 0) { rs[0] = s; rs2[0] = s2; }
    }
    __syncthreads();
    float inv = 1.f / (float)HW;
    float m = rs[0] * inv;
    float v = fmaxf(rs2[0] * inv - m * m, 0.f);
    float r1 = rsqrtf(v + 1e-5f);
    float a = 1.f + r1;
    float r2 = rsqrtf(a * a * v + 1e-5f);
    float scale = a * (r2 + 1.f);
    float shift = -(a * r2 + r1) * m;
    for (int i = threadIdx.x; i < HW; i += blockDim.x)
        yc[i] = fmaf(scale, xc[i], shift);
}

// ---------------------------------------------------------------------------
// Direct 3x3 SAME conv (NCHW, OIHW weights).
// Block = 256 threads (16x16), output tile 16 rows x 32 cols, 2 px/thread,
// OCT output channels per thread in registers. Weights in smem as float4
// (uniform address -> broadcast), input tile in smem.
// ---------------------------------------------------------------------------
template <int CC, int OCT>
__global__ __launch_bounds__(256) void conv3x3_kernel(
    const float* __restrict__ in, const float* __restrict__ w,
    const float* __restrict__ b, float* __restrict__ out,
    int Cin, int Cout, int H, int W)
{
    constexpr int TH = 16, TW = 32;
    __shared__ float sIn[CC][TH + 2][TW + 2];
    __shared__ __align__(16) float sW[CC][9][OCT];

    int tx = threadIdx.x, ty = threadIdx.y;
    int tid = ty * 16 + tx;
    int x0 = blockIdx.x * TW, y0 = blockIdx.y * TH;
    int oc0 = blockIdx.z * OCT;
    int HW = H * W;

    float acc[2][OCT];
    #pragma unroll
    for (int p = 0; p < 2; p++)
        #pragma unroll
        for (int o = 0; o < OCT; o++) acc[p][o] = 0.f;

    for (int cc0 = 0; cc0 < Cin; cc0 += CC) {
        // input tile (zero-padded)
        const int NX = CC * (TH + 2) * (TW + 2);
        for (int idx = tid; idx < NX; idx += 256) {
            int c = idx / ((TH + 2) * (TW + 2));
            int r = idx % ((TH + 2) * (TW + 2));
            int iy = r / (TW + 2), ix = r % (TW + 2);
            int gy = y0 + iy - 1, gx = x0 + ix - 1;
            float v = 0.f;
            if (gy >= 0 && gy < H && gx >= 0 && gx < W)
                v = in[(size_t)(cc0 + c) * HW + (size_t)gy * W + gx];
            sIn[c][iy][ix] = v;
        }
        // weights: sW[c][k][oc] = w[oc0+oc][cc0+c][k]
        const int NW = CC * 9 * OCT;
        for (int idx = tid; idx < NW; idx += 256) {
            int oc = idx % OCT;
            int rem = idx / OCT;
            int k = rem % 9;
            int c = rem / 9;
            int gco = oc0 + oc;
            float v = (gco < Cout) ? w[((size_t)gco * Cin + cc0 + c) * 9 + k] : 0.f;
            sW[c][k][oc] = v;
        }
        __syncthreads();

        #pragma unroll 1
        for (int c = 0; c < CC; c++) {
            float rin[3][4];
            #pragma unroll
            for (int dy = 0; dy < 3; dy++)
                #pragma unroll
                for (int dx = 0; dx < 4; dx++)
                    rin[dy][dx] = sIn[c][ty + dy][2 * tx + dx];
            #pragma unroll
            for (int o4 = 0; o4 < OCT / 4; o4++) {
                #pragma unroll
                for (int k = 0; k < 9; k++) {
                    float4 wv = *reinterpret_cast<const float4*>(&sW[c][k][o4 * 4]);
                    float v0 = rin[k / 3][k % 3];
                    float v1 = rin[k / 3][k % 3 + 1];
                    acc[0][o4 * 4 + 0] = fmaf(v0, wv.x, acc[0][o4 * 4 + 0]);
                    acc[0][o4 * 4 + 1] = fmaf(v0, wv.y, acc[0][o4 * 4 + 1]);
                    acc[0][o4 * 4 + 2] = fmaf(v0, wv.z, acc[0][o4 * 4 + 2]);
                    acc[0][o4 * 4 + 3] = fmaf(v0, wv.w, acc[0][o4 * 4 + 3]);
                    acc[1][o4 * 4 + 0] = fmaf(v1, wv.x, acc[1][o4 * 4 + 0]);
                    acc[1][o4 * 4 + 1] = fmaf(v1, wv.y, acc[1][o4 * 4 + 1]);
                    acc[1][o4 * 4 + 2] = fmaf(v1, wv.z, acc[1][o4 * 4 + 2]);
                    acc[1][o4 * 4 + 3] = fmaf(v1, wv.w, acc[1][o4 * 4 + 3]);
                }
            }
        }
        __syncthreads();
    }

    int gy = y0 + ty;
    #pragma unroll
    for (int o = 0; o < OCT; o++) {
        int gco = oc0 + o;
        if (gco >= Cout) break;
        float bb = b[gco];
        int gx = x0 + 2 * tx;
        out[(size_t)gco * HW + (size_t)gy * W + gx] = acc[0][o] + bb;
        out[(size_t)gco * HW + (size_t)gy * W + gx + 1] = acc[1][o] + bb;
    }
}

// ---------------------------------------------------------------------------
// PAC kernel map: kk4[y][x][t], t = a*2+b over (i_a, j_b).
//   y even: i0=i1=1 (i1 masked);  y odd: i0=0, i1=2 (i1 masked at last row)
//   same for x/j.  kk = exp(-0.5 * sum_c (gpad[y+i, x+j] - g[y,x])^2)
// Invalid terms stored as 0 so the apply kernel is branch-free.
// ---------------------------------------------------------------------------
__global__ void kk_kernel(const float* __restrict__ g, float* __restrict__ kk4,
                          int Cg, int Ho, int Wo)
{
    int xo = blockIdx.x * blockDim.x + threadIdx.x;
    int y = blockIdx.y;
    if (xo >= Wo) return;
    int HW = Ho * Wo;
    bool yodd = (y & 1), xodd = (xo & 1);
    int i0 = yodd ? 0 : 1, i1 = yodd ? 2 : 1;
    int j0 = xodd ? 0 : 1, j1 = xodd ? 2 : 1;
    bool vi1 = yodd && (y < Ho - 1);
    bool vj1 = xodd && (xo < Wo - 1);

    int Ya[2] = { y + i0 - 1, y + i1 - 1 };
    int Xb[2] = { xo + j0 - 1, xo + j1 - 1 };
    bool ib[4];
    int off[4];
    #pragma unroll
    for (int a = 0; a < 2; a++)
        #pragma unroll
        for (int bb = 0; bb < 2; bb++) {
            int t = a * 2 + bb;
            ib[t] = (Ya[a] >= 0 && Ya[a] < Ho && Xb[bb] >= 0 && Xb[bb] < Wo);
            off[t] = Ya[a] * Wo + Xb[bb];
        }
    int base = y * Wo + xo;
    float s0 = 0.f, s1 = 0.f, s2 = 0.f, s3 = 0.f;
    for (int c = 0; c < Cg; c++) {
        const float* gc = g + (size_t)c * HW;
        float gv = gc[base];
        float n0 = ib[0] ? gc[off[0]] : 0.f;
        float n1 = ib[1] ? gc[off[1]] : 0.f;
        float n2 = ib[2] ? gc[off[2]] : 0.f;
        float n3 = ib[3] ? gc[off[3]] : 0.f;
        float d;
        d = n0 - gv; s0 = fmaf(d, d, s0);
        d = n1 - gv; s1 = fmaf(d, d, s1);
        d = n2 - gv; s2 = fmaf(d, d, s2);
        d = n3 - gv; s3 = fmaf(d, d, s3);
    }
    float4 r;
    r.x = expf(-0.5f * s0);
    r.y = vj1 ? expf(-0.5f * s1) : 0.f;
    r.z = vi1 ? expf(-0.5f * s2) : 0.f;
    r.w = (vi1 && vj1) ? expf(-0.5f * s3) : 0.f;
    reinterpret_cast<float4*>(kk4)[base] = r;
}

// ---------------------------------------------------------------------------
// PAC transposed conv apply:
//   out[o,y,x] = b[o] + sum_{a,b} kk_ab(y,x) * sum_c x[c,h_a,w_b]*w[c,o,i_a,j_b]
// Tile = 16 rows x 32 cols, 2 px/thread at (x, x+16) -> identical taps.
// Weight layout (Ci, Co, 3, 3).
// ---------------------------------------------------------------------------
template <int CC, int OCT>
__global__ __launch_bounds__(256) void pac_kernel(
    const float* __restrict__ x, const float* __restrict__ kk4,
    const float* __restrict__ w, const float* __restrict__ b,
    float* __restrict__ out, int Ci, int Co, int Hin, int Ho)
{
    const int Wo = Ho;
    const int Win = Hin;
    constexpr int XH = 9, XW = 17;
    __shared__ float sX[CC][XH][XW];
    __shared__ __align__(16) float sW[CC][9][OCT];

    int tx = threadIdx.x, ty = threadIdx.y;
    int tid = ty * 16 + tx;
    int x0 = blockIdx.x * 32, y0 = blockIdx.y * 16;
    int oc0 = blockIdx.z * OCT;
    int yy = y0 + ty;
    int hb = y0 >> 1, wb = x0 >> 1;
    int HWin = Hin * Win;

    bool yodd = (yy & 1), xodd = (tx & 1);  // x0 is a multiple of 32 -> parity(xo)=parity(tx)
    int i0 = yodd ? 0 : 1, i1 = yodd ? 2 : 1;
    int j0 = xodd ? 0 : 1, j1 = xodd ? 2 : 1;
    int lh0 = (ty + i0 - 1) >> 1;
    int lh1 = (ty + i1 - 1) >> 1;
    int lw0 = (tx + j0 - 1) >> 1;
    int lw1 = (tx + j1 - 1) >> 1;
    int t00 = i0 * 3 + j0, t01 = i0 * 3 + j1, t10 = i1 * 3 + j0, t11 = i1 * 3 + j1;

    float4 kA = reinterpret_cast<const float4*>(kk4)[(size_t)yy * Wo + x0 + tx];
    float4 kB = reinterpret_cast<const float4*>(kk4)[(size_t)yy * Wo + x0 + tx + 16];

    float acc[2][OCT];
    #pragma unroll
    for (int p = 0; p < 2; p++)
        #pragma unroll
        for (int o = 0; o < OCT; o++) acc[p][o] = 0.f;

    for (int cc0 = 0; cc0 < Ci; cc0 += CC) {
        const int NX = CC * XH * XW;
        for (int idx = tid; idx < NX; idx += 256) {
            int c = idx / (XH * XW);
            int r = idx % (XH * XW);
            int ih = r / XW, iw = r % XW;
            int gh = hb + ih, gw = wb + iw;
            float v = 0.f;
            if (gh < Hin && gw < Win)
                v = x[(size_t)(cc0 + c) * HWin + (size_t)gh * Win + gw];
            sX[c][ih][iw] = v;
        }
        const int NW = CC * 9 * OCT;
        for (int idx = tid; idx < NW; idx += 256) {
            int oc = idx % OCT;
            int rem = idx / OCT;
            int tap = rem % 9;
            int c = rem / 9;
            int gco = oc0 + oc;
            float v = (gco < Co) ? w[((size_t)(cc0 + c) * Co + gco) * 9 + tap] : 0.f;
            sW[c][tap][oc] = v;
        }
        __syncthreads();

        #pragma unroll 1
        for (int c = 0; c < CC; c++) {
            float a00 = sX[c][lh0][lw0], a01 = sX[c][lh0][lw1];
            float a10 = sX[c][lh1][lw0], a11 = sX[c][lh1][lw1];
            float b00 = sX[c][lh0][lw0 + 8], b01 = sX[c][lh0][lw1 + 8];
            float b10 = sX[c][lh1][lw0 + 8], b11 = sX[c][lh1][lw1 + 8];
            float qa0 = kA.x * a00, qa1 = kA.y * a01, qa2 = kA.z * a10, qa3 = kA.w * a11;
            float qb0 = kB.x * b00, qb1 = kB.y * b01, qb2 = kB.z * b10, qb3 = kB.w * b11;
            #pragma unroll
            for (int o4 = 0; o4 < OCT / 4; o4++) {
                float4 w0v = *reinterpret_cast<const float4*>(&sW[c][t00][o4 * 4]);
                float4 w1v = *reinterpret_cast<const float4*>(&sW[c][t01][o4 * 4]);
                float4 w2v = *reinterpret_cast<const float4*>(&sW[c][t10][o4 * 4]);
                float4 w3v = *reinterpret_cast<const float4*>(&sW[c][t11][o4 * 4]);
                int ob = o4 * 4;
                acc[0][ob + 0] = fmaf(qa0, w0v.x, acc[0][ob + 0]);
                acc[0][ob + 0] = fmaf(qa1, w1v.x, acc[0][ob + 0]);
                acc[0][ob + 0] = fmaf(qa2, w2v.x, acc[0][ob + 0]);
                acc[0][ob + 0] = fmaf(qa3, w3v.x, acc[0][ob + 0]);
                acc[0][ob + 1] = fmaf(qa0, w0v.y, acc[0][ob + 1]);
                acc[0][ob + 1] = fmaf(qa1, w1v.y, acc[0][ob + 1]);
                acc[0][ob + 1] = fmaf(qa2, w2v.y, acc[0][ob + 1]);
                acc[0][ob + 1] = fmaf(qa3, w3v.y, acc[0][ob + 1]);
                acc[0][ob + 2] = fmaf(qa0, w0v.z, acc[0][ob + 2]);
                acc[0][ob + 2] = fmaf(qa1, w1v.z, acc[0][ob + 2]);
                acc[0][ob + 2] = fmaf(qa2, w2v.z, acc[0][ob + 2]);
                acc[0][ob + 2] = fmaf(qa3, w3v.z, acc[0][ob + 2]);
                acc[0][ob + 3] = fmaf(qa0, w0v.w, acc[0][ob + 3]);
                acc[0][ob + 3] = fmaf(qa1, w1v.w, acc[0][ob + 3]);
                acc[0][ob + 3] = fmaf(qa2, w2v.w, acc[0][ob + 3]);
                acc[0][ob + 3] = fmaf(qa3, w3v.w, acc[0][ob + 3]);
                acc[1][ob + 0] = fmaf(qb0, w0v.x, acc[1][ob + 0]);
                acc[1][ob + 0] = fmaf(qb1, w1v.x, acc[1][ob + 0]);
                acc[1][ob + 0] = fmaf(qb2, w2v.x, acc[1][ob + 0]);
                acc[1][ob + 0] = fmaf(qb3, w3v.x, acc[1][ob + 0]);
                acc[1][ob + 1] = fmaf(qb0, w0v.y, acc[1][ob + 1]);
                acc[1][ob + 1] = fmaf(qb1, w1v.y, acc[1][ob + 1]);
                acc[1][ob + 1] = fmaf(qb2, w2v.y, acc[1][ob + 1]);
                acc[1][ob + 1] = fmaf(qb3, w3v.y, acc[1][ob + 1]);
                acc[1][ob + 2] = fmaf(qb0, w0v.z, acc[1][ob + 2]);
                acc[1][ob + 2] = fmaf(qb1, w1v.z, acc[1][ob + 2]);
                acc[1][ob + 2] = fmaf(qb2, w2v.z, acc[1][ob + 2]);
                acc[1][ob + 2] = fmaf(qb3, w3v.z, acc[1][ob + 2]);
                acc[1][ob + 3] = fmaf(qb0, w0v.w, acc[1][ob + 3]);
                acc[1][ob + 3] = fmaf(qb1, w1v.w, acc[1][ob + 3]);
                acc[1][ob + 3] = fmaf(qb2, w2v.w, acc[1][ob + 3]);
                acc[1][ob + 3] = fmaf(qb3, w3v.w, acc[1][ob + 3]);
            }
        }
        __syncthreads();
    }

    size_t HWo = (size_t)Ho * Wo;
    #pragma unroll
    for (int o = 0; o < OCT; o++) {
        int gco = oc0 + o;
        if (gco >= Co) break;
        float bb = b[gco];
        out[(size_t)gco * HWo + (size_t)yy * Wo + x0 + tx] = acc[0][o] + bb;
        out[(size_t)gco * HWo + (size_t)yy * Wo + x0 + tx + 16] = acc[1][o] + bb;
    }
}

// ---------------------------------------------------------------------------
// Launcher
// ---------------------------------------------------------------------------
extern "C" void kernel_launch(void* const* d_in, const int* in_sizes, int n_in,
                              void* d_out, int out_size)
{
    (void)in_sizes; (void)n_in; (void)out_size;
    const float* x      = (const float*)d_in[0];
    const float* ef2    = (const float*)d_in[1];
    const float* ef1    = (const float*)d_in[2];
    const float* w_adj2 = (const float*)d_in[3];
    const float* b_adj2 = (const float*)d_in[4];
    const float* w_adj1 = (const float*)d_in[5];
    const float* b_adj1 = (const float*)d_in[6];
    const float* w_p16  = (const float*)d_in[7];
    const float* b_p16  = (const float*)d_in[8];
    const float* w_p20  = (const float*)d_in[9];
    const float* b_p20  = (const float*)d_in[10];
    const float* w_o    = (const float*)d_in[11];
    const float* b_o    = (const float*)d_in[12];
    float* out = (float*)d_out;

    float *px0, *pg2, *pk16, *px1, *pg1, *pk20, *px2;
    cudaGetSymbolAddress((void**)&px0, g_x0);
    cudaGetSymbolAddress((void**)&pg2, g_g2);
    cudaGetSymbolAddress((void**)&pk16, g_kk16);
    cudaGetSymbolAddress((void**)&px1, g_x1);
    cudaGetSymbolAddress((void**)&pg1, g_g1);
    cudaGetSymbolAddress((void**)&pk20, g_kk20);
    cudaGetSymbolAddress((void**)&px2, g_x2);

    dim3 blk(16, 16);

    // x = inorm(inorm(x)+x)+...  (fused analytically)
    inorm2_kernel<<<256, 256>>>(x, px0, 64 * 64);

    // g2 = conv3x3(ef_lv2): 128 -> 256 @ 128x128
    conv3x3_kernel<8, 16><<<dim3(4, 8, 16), blk>>>(ef2, w_adj2, b_adj2, pg2, 128, 256, 128, 128);

    // kk for pac16 (guide channels = 256, Ho = 128)
    kk_kernel<<<dim3(1, 128), 128>>>(pg2, pk16, 256, 128, 128);

    // pac16: 256 -> 128, out 128x128
    pac_kernel<16, 16><<<dim3(4, 8, 8), blk>>>(px0, pk16, w_p16, b_p16, px1, 256, 128, 64, 128);

    // double inorm+res (in place)
    inorm2_kernel<<<128, 256>>>(px1, px1, 128 * 128);

    // g1 = conv3x3(ef_lv1): 64 -> 128 @ 256x256
    conv3x3_kernel<8, 16><<<dim3(8, 16, 8), blk>>>(ef1, w_adj1, b_adj1, pg1, 64, 128, 256, 256);

    // kk for pac20 (guide channels = 128, Ho = 256)
    kk_kernel<<<dim3(1, 256), 256>>>(pg1, pk20, 128, 256, 256);

    // pac20: 128 -> 64, out 256x256
    pac_kernel<16, 16><<<dim3(8, 16, 4), blk>>>(px1, pk20, w_p20, b_p20, px2, 128, 64, 128, 256);

    // double inorm+res (in place)
    inorm2_kernel<<<64, 256>>>(px2, px2, 256 * 256);

    // final conv: 64 -> 3 @ 256x256 straight into d_out
    conv3x3_kernel<8, 4><<<dim3(8, 16, 1), blk>>>(px2, w_o, b_o, out, 64, 3, 256, 256);
}

// round 5
// speedup vs baseline: 1.0481x; 1.0481x over previous
#include <cuda_runtime.h>
#include <math.h>

// ---------------------------------------------------------------------------
// Static device scratch (no allocations allowed)
// ---------------------------------------------------------------------------
__device__ float g_x0[256 * 64 * 64];     // x after double inorm        (4 MB)
__device__ float g_g2[256 * 128 * 128];   // guide lv2                   (16 MB)
__device__ float g_kk16[128 * 128 * 4];   // kk map for pac16
__device__ float g_x1[128 * 128 * 128];   // pac16 out / inorm in-place  (8 MB)
__device__ float g_g1[128 * 256 * 256];   // guide lv1                   (32 MB)
__device__ float g_kk20[256 * 256 * 4];   // kk map for pac20
__device__ float g_x2[64 * 256 * 256];    // pac20 out / inorm in-place  (16 MB)

// ---------------------------------------------------------------------------
// Fused double (instance-norm + residual):
//   y = inorm(x)+x applied twice == scale*x + shift with
//   r1 = rsqrt(v+eps), a = 1+r1, r2 = rsqrt(a*a*v+eps)
//   scale = a*(r2+1), shift = -(a*r2 + r1)*m
// ---------------------------------------------------------------------------
__global__ void inorm2_kernel(const float* x, float* y, int HW) {
    int c = blockIdx.x;
    const float* xc = x + (size_t)c * HW;
    float* yc = y + (size_t)c * HW;

    float s = 0.f, s2 = 0.f;
    for (int i = threadIdx.x; i < HW; i += blockDim.x) {
        float v = xc[i];
        s += v;
        s2 = fmaf(v, v, s2);
    }
    __shared__ float rs[32], rs2[32];
    #pragma unroll
    for (int o = 16; o; o >>= 1) {
        s += __shfl_xor_sync(0xFFFFFFFFu, s, o);
        s2 += __shfl_xor_sync(0xFFFFFFFFu, s2, o);
    }
    int w = threadIdx.x >> 5, l = threadIdx.x & 31;
    if (l == 0) { rs[w] = s; rs2[w] = s2; }
    __syncthreads();
    int nw = blockDim.x >> 5;
    if (w == 0) {
        s = (l < nw) ? rs[l] : 0.f;
        s2 = (l < nw) ? rs2[l] : 0.f;
        #pragma unroll
        for (int o = 16; o; o >>= 1) {
            s += __shfl_xor_sync(0xFFFFFFFFu, s, o);
            s2 += __shfl_xor_sync(0xFFFFFFFFu, s2, o);
        }
        if (l == 0) { rs[0] = s; rs2[0] = s2; }
    }
    __syncthreads();
    float inv = 1.f / (float)HW;
    float m = rs[0] * inv;
    float v = fmaxf(rs2[0] * inv - m * m, 0.f);
    float r1 = rsqrtf(v + 1e-5f);
    float a = 1.f + r1;
    float r2 = rsqrtf(a * a * v + 1e-5f);
    float scale = a * (r2 + 1.f);
    float shift = -(a * r2 + r1) * m;
    for (int i = threadIdx.x; i < HW; i += blockDim.x)
        yc[i] = fmaf(scale, xc[i], shift);
}

// ---------------------------------------------------------------------------
// Direct 3x3 SAME conv (NCHW, OIHW weights).
// Block = 128 threads (16x8). Each thread computes a 2x2 output patch,
// OCT output channels. Output tile = 16 rows x 32 cols.
// ---------------------------------------------------------------------------
template <int CC, int OCT>
__global__ __launch_bounds__(128) void conv3x3_kernel(
    const float* __restrict__ in, const float* __restrict__ w,
    const float* __restrict__ b, float* __restrict__ out,
    int Cin, int Cout, int H, int W)
{
    constexpr int TH = 16, TW = 32;
    __shared__ float sIn[CC][TH + 2][TW + 2];
    __shared__ __align__(16) float sW[CC][9][OCT];

    int tx = threadIdx.x, ty = threadIdx.y;       // (16, 8)
    int tid = ty * 16 + tx;
    int x0 = blockIdx.x * TW, y0 = blockIdx.y * TH;
    int oc0 = blockIdx.z * OCT;
    int HW = H * W;

    float acc[4][OCT];   // [py*2 + px][oc]
    #pragma unroll
    for (int p = 0; p < 4; p++)
        #pragma unroll
        for (int o = 0; o < OCT; o++) acc[p][o] = 0.f;

    for (int cc0 = 0; cc0 < Cin; cc0 += CC) {
        // input tile (zero-padded)
        const int NX = CC * (TH + 2) * (TW + 2);
        for (int idx = tid; idx < NX; idx += 128) {
            int c = idx / ((TH + 2) * (TW + 2));
            int r = idx % ((TH + 2) * (TW + 2));
            int iy = r / (TW + 2), ix = r % (TW + 2);
            int gy = y0 + iy - 1, gx = x0 + ix - 1;
            float v = 0.f;
            if (gy >= 0 && gy < H && gx >= 0 && gx < W)
                v = in[(size_t)(cc0 + c) * HW + (size_t)gy * W + gx];
            sIn[c][iy][ix] = v;
        }
        // weights: sW[c][k][oc] = w[oc0+oc][cc0+c][k]
        const int NW = CC * 9 * OCT;
        for (int idx = tid; idx < NW; idx += 128) {
            int oc = idx % OCT;
            int rem = idx / OCT;
            int k = rem % 9;
            int c = rem / 9;
            int gco = oc0 + oc;
            float v = (gco < Cout) ? w[((size_t)gco * Cin + cc0 + c) * 9 + k] : 0.f;
            sW[c][k][oc] = v;
        }
        __syncthreads();

        #pragma unroll 1
        for (int c = 0; c < CC; c++) {
            // 4x4 input patch for the 2x2 output quad, via float2 loads
            float rin[4][4];
            #pragma unroll
            for (int dy = 0; dy < 4; dy++) {
                float2 v0 = *reinterpret_cast<const float2*>(&sIn[c][2 * ty + dy][2 * tx]);
                float2 v1 = *reinterpret_cast<const float2*>(&sIn[c][2 * ty + dy][2 * tx + 2]);
                rin[dy][0] = v0.x; rin[dy][1] = v0.y;
                rin[dy][2] = v1.x; rin[dy][3] = v1.y;
            }
            #pragma unroll
            for (int o4 = 0; o4 < OCT / 4; o4++) {
                #pragma unroll
                for (int k = 0; k < 9; k++) {
                    float4 wv = *reinterpret_cast<const float4*>(&sW[c][k][o4 * 4]);
                    int ky = k / 3, kx = k % 3;
                    #pragma unroll
                    for (int py = 0; py < 2; py++) {
                        #pragma unroll
                        for (int px = 0; px < 2; px++) {
                            float v = rin[py + ky][px + kx];
                            int p = py * 2 + px;
                            acc[p][o4 * 4 + 0] = fmaf(v, wv.x, acc[p][o4 * 4 + 0]);
                            acc[p][o4 * 4 + 1] = fmaf(v, wv.y, acc[p][o4 * 4 + 1]);
                            acc[p][o4 * 4 + 2] = fmaf(v, wv.z, acc[p][o4 * 4 + 2]);
                            acc[p][o4 * 4 + 3] = fmaf(v, wv.w, acc[p][o4 * 4 + 3]);
                        }
                    }
                }
            }
        }
        __syncthreads();
    }

    int gx = x0 + 2 * tx;
    #pragma unroll
    for (int o = 0; o < OCT; o++) {
        int gco = oc0 + o;
        if (gco >= Cout) break;
        float bb = b[gco];
        #pragma unroll
        for (int py = 0; py < 2; py++) {
            int gy = y0 + 2 * ty + py;
            float2 v = make_float2(acc[py * 2 + 0][o] + bb, acc[py * 2 + 1][o] + bb);
            *reinterpret_cast<float2*>(&out[(size_t)gco * HW + (size_t)gy * W + gx]) = v;
        }
    }
}

// ---------------------------------------------------------------------------
// PAC kernel map: kk4[y][x][t], t = a*2+b over (i_a, j_b).
// Channel-parallel: block (32 px, 8 channel-groups) with smem reduction.
// Invalid terms stored as 0 so the apply kernel is branch-free.
// ---------------------------------------------------------------------------
__global__ __launch_bounds__(256) void kk_kernel(
    const float* __restrict__ g, float* __restrict__ kk4,
    int Cg, int Ho, int Wo)
{
    int tx = threadIdx.x;        // 0..31 (pixel)
    int grp = threadIdx.y;       // 0..7  (channel group)
    int xo = blockIdx.x * 32 + tx;
    int y = blockIdx.y;
    int HW = Ho * Wo;
    bool yodd = (y & 1), xodd = (xo & 1);
    int i0 = yodd ? 0 : 1, i1 = yodd ? 2 : 1;
    int j0 = xodd ? 0 : 1, j1 = xodd ? 2 : 1;
    bool vi1 = yodd && (y < Ho - 1);
    bool vj1 = xodd && (xo < Wo - 1);

    int Ya[2] = { y + i0 - 1, y + i1 - 1 };
    int Xb[2] = { xo + j0 - 1, xo + j1 - 1 };
    bool ib[4];
    int off[4];
    #pragma unroll
    for (int a = 0; a < 2; a++)
        #pragma unroll
        for (int bb = 0; bb < 2; bb++) {
            int t = a * 2 + bb;
            ib[t] = (Ya[a] >= 0 && Ya[a] < Ho && Xb[bb] >= 0 && Xb[bb] < Wo);
            off[t] = Ya[a] * Wo + Xb[bb];
        }
    int base = y * Wo + xo;
    float s0 = 0.f, s1 = 0.f, s2 = 0.f, s3 = 0.f;
    for (int c = grp; c < Cg; c += 8) {
        const float* gc = g + (size_t)c * HW;
        float gv = gc[base];
        float n0 = ib[0] ? gc[off[0]] : 0.f;
        float n1 = ib[1] ? gc[off[1]] : 0.f;
        float n2 = ib[2] ? gc[off[2]] : 0.f;
        float n3 = ib[3] ? gc[off[3]] : 0.f;
        float d;
        d = n0 - gv; s0 = fmaf(d, d, s0);
        d = n1 - gv; s1 = fmaf(d, d, s1);
        d = n2 - gv; s2 = fmaf(d, d, s2);
        d = n3 - gv; s3 = fmaf(d, d, s3);
    }
    __shared__ float4 red[8][32];
    red[grp][tx] = make_float4(s0, s1, s2, s3);
    __syncthreads();
    if (grp == 0) {
        s0 = 0.f; s1 = 0.f; s2 = 0.f; s3 = 0.f;
        #pragma unroll
        for (int gidx = 0; gidx < 8; gidx++) {
            float4 v = red[gidx][tx];
            s0 += v.x; s1 += v.y; s2 += v.z; s3 += v.w;
        }
        float4 r;
        r.x = expf(-0.5f * s0);
        r.y = vj1 ? expf(-0.5f * s1) : 0.f;
        r.z = vi1 ? expf(-0.5f * s2) : 0.f;
        r.w = (vi1 && vj1) ? expf(-0.5f * s3) : 0.f;
        reinterpret_cast<float4*>(kk4)[base] = r;
    }
}

// ---------------------------------------------------------------------------
// PAC transposed conv apply — quad-parity reformulation.
// Each thread computes a 2x2 output quad at (2Y, 2X). The quad touches input
// pixels (Y..Y+1, X..X+1) and uses each of the 9 weight taps exactly once:
//   o00=(2Y,2X)    : tap(1,1)·in00
//   o01=(2Y,2X+1)  : tap(1,0)·in00 + tap(1,2)·in01
//   o10=(2Y+1,2X)  : tap(0,1)·in00 + tap(2,1)·in10
//   o11=(2Y+1,2X+1): tap(0,0)·in00 + tap(0,2)·in01 + tap(2,0)·in10 + tap(2,2)·in11
// Each term is scaled by the kk entry of its (output px, tap); invalid/boundary
// entries in the kk map are already 0.
// Block = 128 threads (16x8 quads) -> output tile 32x16. Weights (Ci,Co,3,3).
// ---------------------------------------------------------------------------
template <int CC, int OCT>
__global__ __launch_bounds__(128) void pac_kernel(
    const float* __restrict__ x, const float* __restrict__ kk4,
    const float* __restrict__ w, const float* __restrict__ b,
    float* __restrict__ out, int Ci, int Co, int Hin, int Ho)
{
    const int Wo = Ho;
    const int Win = Hin;
    constexpr int QX = 16, QY = 8;          // quads per block
    constexpr int XH = QY + 1, XW = QX + 2; // 9 x 18 input tile (17 used + pad)
    __shared__ float sX[CC][XH][XW];
    __shared__ __align__(16) float sW[CC][9][OCT];

    int tx = threadIdx.x, ty = threadIdx.y; // (16, 8)
    int tid = ty * 16 + tx;
    int qx0 = blockIdx.x * QX, qy0 = blockIdx.y * QY;
    int oc0 = blockIdx.z * OCT;
    int ox0 = 2 * (qx0 + tx), oy0 = 2 * (qy0 + ty);
    int HWin = Hin * Win;

    const float4* kp = reinterpret_cast<const float4*>(kk4);
    float4 kq00 = kp[(size_t)oy0 * Wo + ox0];
    float4 kq01 = kp[(size_t)oy0 * Wo + ox0 + 1];
    float4 kq10 = kp[(size_t)(oy0 + 1) * Wo + ox0];
    float4 kq11 = kp[(size_t)(oy0 + 1) * Wo + ox0 + 1];
    float k11 = kq00.x;
    float k10 = kq01.x, k12 = kq01.y;
    float k01 = kq10.x, k21 = kq10.z;
    float k00 = kq11.x, k02 = kq11.y, k20 = kq11.z, k22 = kq11.w;

    float acc[4][OCT];  // [0]=o00 [1]=o01 [2]=o10 [3]=o11
    #pragma unroll
    for (int p = 0; p < 4; p++)
        #pragma unroll
        for (int o = 0; o < OCT; o++) acc[p][o] = 0.f;

    for (int cc0 = 0; cc0 < Ci; cc0 += CC) {
        const int NX = CC * XH * XW;
        for (int idx = tid; idx < NX; idx += 128) {
            int c = idx / (XH * XW);
            int r = idx % (XH * XW);
            int ih = r / XW, iw = r % XW;
            int gh = qy0 + ih, gw = qx0 + iw;
            float v = 0.f;
            if (gh < Hin && gw < Win)
                v = x[(size_t)(cc0 + c) * HWin + (size_t)gh * Win + gw];
            sX[c][ih][iw] = v;
        }
        const int NW = CC * 9 * OCT;
        for (int idx = tid; idx < NW; idx += 128) {
            int oc = idx % OCT;
            int rem = idx / OCT;
            int tap = rem % 9;
            int c = rem / 9;
            int gco = oc0 + oc;
            float v = (gco < Co) ? w[((size_t)(cc0 + c) * Co + gco) * 9 + tap] : 0.f;
            sW[c][tap][oc] = v;
        }
        __syncthreads();

        #pragma unroll 1
        for (int c = 0; c < CC; c++) {
            float in00 = sX[c][ty][tx],     in01 = sX[c][ty][tx + 1];
            float in10 = sX[c][ty + 1][tx], in11 = sX[c][ty + 1][tx + 1];
            float p11 = k11 * in00;
            float p10 = k10 * in00, p12 = k12 * in01;
            float p01 = k01 * in00, p21 = k21 * in10;
            float p00 = k00 * in00, p02 = k02 * in01;
            float p20 = k20 * in10, p22 = k22 * in11;
            #pragma unroll
            for (int o4 = 0; o4 < OCT / 4; o4++) {
                int ob = o4 * 4;
                float4 wv;
                // tap 4 = (1,1) -> o00
                wv = *reinterpret_cast<const float4*>(&sW[c][4][ob]);
                acc[0][ob + 0] = fmaf(p11, wv.x, acc[0][ob + 0]);
                acc[0][ob + 1] = fmaf(p11, wv.y, acc[0][ob + 1]);
                acc[0][ob + 2] = fmaf(p11, wv.z, acc[0][ob + 2]);
                acc[0][ob + 3] = fmaf(p11, wv.w, acc[0][ob + 3]);
                // tap 3 = (1,0) -> o01
                wv = *reinterpret_cast<const float4*>(&sW[c][3][ob]);
                acc[1][ob + 0] = fmaf(p10, wv.x, acc[1][ob + 0]);
                acc[1][ob + 1] = fmaf(p10, wv.y, acc[1][ob + 1]);
                acc[1][ob + 2] = fmaf(p10, wv.z, acc[1][ob + 2]);
                acc[1][ob + 3] = fmaf(p10, wv.w, acc[1][ob + 3]);
                // tap 5 = (1,2) -> o01
                wv = *reinterpret_cast<const float4*>(&sW[c][5][ob]);
                acc[1][ob + 0] = fmaf(p12, wv.x, acc[1][ob + 0]);
                acc[1][ob + 1] = fmaf(p12, wv.y, acc[1][ob + 1]);
                acc[1][ob + 2] = fmaf(p12, wv.z, acc[1][ob + 2]);
                acc[1][ob + 3] = fmaf(p12, wv.w, acc[1][ob + 3]);
                // tap 1 = (0,1) -> o10
                wv = *reinterpret_cast<const float4*>(&sW[c][1][ob]);
                acc[2][ob + 0] = fmaf(p01, wv.x, acc[2][ob + 0]);
                acc[2][ob + 1] = fmaf(p01, wv.y, acc[2][ob + 1]);
                acc[2][ob + 2] = fmaf(p01, wv.z, acc[2][ob + 2]);
                acc[2][ob + 3] = fmaf(p01, wv.w, acc[2][ob + 3]);
                // tap 7 = (2,1) -> o10
                wv = *reinterpret_cast<const float4*>(&sW[c][7][ob]);
                acc[2][ob + 0] = fmaf(p21, wv.x, acc[2][ob + 0]);
                acc[2][ob + 1] = fmaf(p21, wv.y, acc[2][ob + 1]);
                acc[2][ob + 2] = fmaf(p21, wv.z, acc[2][ob + 2]);
                acc[2][ob + 3] = fmaf(p21, wv.w, acc[2][ob + 3]);
                // tap 0 = (0,0) -> o11
                wv = *reinterpret_cast<const float4*>(&sW[c][0][ob]);
                acc[3][ob + 0] = fmaf(p00, wv.x, acc[3][ob + 0]);
                acc[3][ob + 1] = fmaf(p00, wv.y, acc[3][ob + 1]);
                acc[3][ob + 2] = fmaf(p00, wv.z, acc[3][ob + 2]);
                acc[3][ob + 3] = fmaf(p00, wv.w, acc[3][ob + 3]);
                // tap 2 = (0,2) -> o11
                wv = *reinterpret_cast<const float4*>(&sW[c][2][ob]);
                acc[3][ob + 0] = fmaf(p02, wv.x, acc[3][ob + 0]);
                acc[3][ob + 1] = fmaf(p02, wv.y, acc[3][ob + 1]);
                acc[3][ob + 2] = fmaf(p02, wv.z, acc[3][ob + 2]);
                acc[3][ob + 3] = fmaf(p02, wv.w, acc[3][ob + 3]);
                // tap 6 = (2,0) -> o11
                wv = *reinterpret_cast<const float4*>(&sW[c][6][ob]);
                acc[3][ob + 0] = fmaf(p20, wv.x, acc[3][ob + 0]);
                acc[3][ob + 1] = fmaf(p20, wv.y, acc[3][ob + 1]);
                acc[3][ob + 2] = fmaf(p20, wv.z, acc[3][ob + 2]);
                acc[3][ob + 3] = fmaf(p20, wv.w, acc[3][ob + 3]);
                // tap 8 = (2,2) -> o11
                wv = *reinterpret_cast<const float4*>(&sW[c][8][ob]);
                acc[3][ob + 0] = fmaf(p22, wv.x, acc[3][ob + 0]);
                acc[3][ob + 1] = fmaf(p22, wv.y, acc[3][ob + 1]);
                acc[3][ob + 2] = fmaf(p22, wv.z, acc[3][ob + 2]);
                acc[3][ob + 3] = fmaf(p22, wv.w, acc[3][ob + 3]);
            }
        }
        __syncthreads();
    }

    size_t HWo = (size_t)Ho * Wo;
    #pragma unroll
    for (int o = 0; o < OCT; o++) {
        int gco = oc0 + o;
        if (gco >= Co) break;
        float bb = b[gco];
        float2 v0 = make_float2(acc[0][o] + bb, acc[1][o] + bb);
        float2 v1 = make_float2(acc[2][o] + bb, acc[3][o] + bb);
        *reinterpret_cast<float2*>(&out[(size_t)gco * HWo + (size_t)oy0 * Wo + ox0]) = v0;
        *reinterpret_cast<float2*>(&out[(size_t)gco * HWo + (size_t)(oy0 + 1) * Wo + ox0]) = v1;
    }
}

// ---------------------------------------------------------------------------
// Launcher
// ---------------------------------------------------------------------------
extern "C" void kernel_launch(void* const* d_in, const int* in_sizes, int n_in,
                              void* d_out, int out_size)
{
    (void)in_sizes; (void)n_in; (void)out_size;
    const float* x      = (const float*)d_in[0];
    const float* ef2    = (const float*)d_in[1];
    const float* ef1    = (const float*)d_in[2];
    const float* w_adj2 = (const float*)d_in[3];
    const float* b_adj2 = (const float*)d_in[4];
    const float* w_adj1 = (const float*)d_in[5];
    const float* b_adj1 = (const float*)d_in[6];
    const float* w_p16  = (const float*)d_in[7];
    const float* b_p16  = (const float*)d_in[8];
    const float* w_p20  = (const float*)d_in[9];
    const float* b_p20  = (const float*)d_in[10];
    const float* w_o    = (const float*)d_in[11];
    const float* b_o    = (const float*)d_in[12];
    float* out = (float*)d_out;

    float *px0, *pg2, *pk16, *px1, *pg1, *pk20, *px2;
    cudaGetSymbolAddress((void**)&px0, g_x0);
    cudaGetSymbolAddress((void**)&pg2, g_g2);
    cudaGetSymbolAddress((void**)&pk16, g_kk16);
    cudaGetSymbolAddress((void**)&px1, g_x1);
    cudaGetSymbolAddress((void**)&pg1, g_g1);
    cudaGetSymbolAddress((void**)&pk20, g_kk20);
    cudaGetSymbolAddress((void**)&px2, g_x2);

    dim3 blk(16, 8);
    dim3 kblk(32, 8);

    // x = double inorm+residual (fused analytically)
    inorm2_kernel<<<256, 256>>>(x, px0, 64 * 64);

    // g2 = conv3x3(ef_lv2): 128 -> 256 @ 128x128
    conv3x3_kernel<8, 8><<<dim3(4, 8, 32), blk>>>(ef2, w_adj2, b_adj2, pg2, 128, 256, 128, 128);

    // kk for pac16 (guide channels = 256, Ho = 128)
    kk_kernel<<<dim3(4, 128), kblk>>>(pg2, pk16, 256, 128, 128);

    // pac16: 256 -> 128, out 128x128
    pac_kernel<8, 8><<<dim3(4, 8, 16), blk>>>(px0, pk16, w_p16, b_p16, px1, 256, 128, 64, 128);

    // double inorm+res (in place)
    inorm2_kernel<<<128, 256>>>(px1, px1, 128 * 128);

    // g1 = conv3x3(ef_lv1): 64 -> 128 @ 256x256
    conv3x3_kernel<8, 8><<<dim3(8, 16, 16), blk>>>(ef1, w_adj1, b_adj1, pg1, 64, 128, 256, 256);

    // kk for pac20 (guide channels = 128, Ho = 256)
    kk_kernel<<<dim3(8, 256), kblk>>>(pg1, pk20, 128, 256, 256);

    // pac20: 128 -> 64, out 256x256
    pac_kernel<8, 8><<<dim3(8, 16, 8), blk>>>(px1, pk20, w_p20, b_p20, px2, 128, 64, 128, 256);

    // double inorm+res (in place)
    inorm2_kernel<<<64, 256>>>(px2, px2, 256 * 256);

    // final conv: 64 -> 3 @ 256x256 straight into d_out
    conv3x3_kernel<8, 4><<<dim3(8, 16, 1), blk>>>(px2, w_o, b_o, out, 64, 3, 256, 256);
}

// round 6
// speedup vs baseline: 1.1062x; 1.0554x over previous
#include <cuda_runtime.h>
#include <math.h>

// ---------------------------------------------------------------------------
// Static device scratch (no allocations allowed)
// ---------------------------------------------------------------------------
__device__ float g_x0[256 * 64 * 64];     // x after double inorm        (4 MB)
__device__ float g_g2[256 * 128 * 128];   // guide lv2                   (16 MB)
__device__ float g_kk16[128 * 128 * 4];   // kk map for pac16
__device__ float g_x1[128 * 128 * 128];   // pac16 out / inorm in-place  (8 MB)
__device__ float g_g1[128 * 256 * 256];   // guide lv1                   (32 MB)
__device__ float g_kk20[256 * 256 * 4];   // kk map for pac20
__device__ float g_x2[64 * 256 * 256];    // pac20 out / inorm in-place  (16 MB)

// ---------------------------------------------------------------------------
// Packed f32x2 helpers (2 fp32 FMAs per issue slot on sm_103a)
// ---------------------------------------------------------------------------
typedef unsigned long long u64;

__device__ __forceinline__ u64 pk2(float x, float y) {
    u64 r;
    asm("mov.b64 %0, {%1, %2};" : "=l"(r) : "f"(x), "f"(y));
    return r;
}
__device__ __forceinline__ void fma2(u64& d, u64 a, u64 b) {
    asm("fma.rn.f32x2 %0, %1, %2, %3;" : "=l"(d) : "l"(a), "l"(b), "l"(d));
}
__device__ __forceinline__ float2 up2(u64 v) {
    float lo, hi;
    asm("mov.b64 {%0, %1}, %2;" : "=f"(lo), "=f"(hi) : "l"(v));
    return make_float2(lo, hi);
}

// ---------------------------------------------------------------------------
// Fused double (instance-norm + residual):
//   y = inorm(x)+x applied twice == scale*x + shift
// ---------------------------------------------------------------------------
__global__ void inorm2_kernel(const float* x, float* y, int HW) {
    int c = blockIdx.x;
    const float* xc = x + (size_t)c * HW;
    float* yc = y + (size_t)c * HW;

    float s = 0.f, s2 = 0.f;
    for (int i = threadIdx.x; i < HW; i += blockDim.x) {
        float v = xc[i];
        s += v;
        s2 = fmaf(v, v, s2);
    }
    __shared__ float rs[32], rs2[32];
    #pragma unroll
    for (int o = 16; o; o >>= 1) {
        s += __shfl_xor_sync(0xFFFFFFFFu, s, o);
        s2 += __shfl_xor_sync(0xFFFFFFFFu, s2, o);
    }
    int w = threadIdx.x >> 5, l = threadIdx.x & 31;
    if (l == 0) { rs[w] = s; rs2[w] = s2; }
    __syncthreads();
    int nw = blockDim.x >> 5;
    if (w == 0) {
        s = (l < nw) ? rs[l] : 0.f;
        s2 = (l < nw) ? rs2[l] : 0.f;
        #pragma unroll
        for (int o = 16; o; o >>= 1) {
            s += __shfl_xor_sync(0xFFFFFFFFu, s, o);
            s2 += __shfl_xor_sync(0xFFFFFFFFu, s2, o);
        }
        if (l == 0) { rs[0] = s; rs2[0] = s2; }
    }
    __syncthreads();
    float inv = 1.f / (float)HW;
    float m = rs[0] * inv;
    float v = fmaxf(rs2[0] * inv - m * m, 0.f);
    float r1 = rsqrtf(v + 1e-5f);
    float a = 1.f + r1;
    float r2 = rsqrtf(a * a * v + 1e-5f);
    float scale = a * (r2 + 1.f);
    float shift = -(a * r2 + r1) * m;
    for (int i = threadIdx.x; i < HW; i += blockDim.x)
        yc[i] = fmaf(scale, xc[i], shift);
}

// ---------------------------------------------------------------------------
// Direct 3x3 SAME conv (NCHW, OIHW weights), packed f32x2 over oc pairs.
// Block = 128 threads (16x8). Each thread computes PY x 2 output pixels,
// OCT output channels (as OCT/2 packed accumulators per pixel).
// Output tile = 8*PY rows x 32 cols.
// ---------------------------------------------------------------------------
template <int CC, int OCT, int PY>
__global__ __launch_bounds__(128) void conv3x3_kernel(
    const float* __restrict__ in, const float* __restrict__ w,
    const float* __restrict__ b, float* __restrict__ out,
    int Cin, int Cout, int H, int W)
{
    constexpr int TH = 8 * PY, TW = 32;
    constexpr int NP = 2 * PY;
    constexpr int NJ = OCT / 2;
    __shared__ float sIn[CC][TH + 2][TW + 2];
    __shared__ __align__(16) float sW[CC][9][OCT];

    int tx = threadIdx.x, ty = threadIdx.y;       // (16, 8)
    int tid = ty * 16 + tx;
    int x0 = blockIdx.x * TW, y0 = blockIdx.y * TH;
    int oc0 = blockIdx.z * OCT;
    int HW = H * W;

    u64 acc[NP][NJ];
    #pragma unroll
    for (int p = 0; p < NP; p++)
        #pragma unroll
        for (int j = 0; j < NJ; j++) acc[p][j] = 0ull;

    for (int cc0 = 0; cc0 < Cin; cc0 += CC) {
        // input tile (zero-padded)
        const int NX = CC * (TH + 2) * (TW + 2);
        for (int idx = tid; idx < NX; idx += 128) {
            int c = idx / ((TH + 2) * (TW + 2));
            int r = idx % ((TH + 2) * (TW + 2));
            int iy = r / (TW + 2), ix = r % (TW + 2);
            int gy = y0 + iy - 1, gx = x0 + ix - 1;
            float v = 0.f;
            if (gy >= 0 && gy < H && gx >= 0 && gx < W)
                v = in[(size_t)(cc0 + c) * HW + (size_t)gy * W + gx];
            sIn[c][iy][ix] = v;
        }
        // weights: sW[c][k][oc] = w[oc0+oc][cc0+c][k]
        const int NW = CC * 9 * OCT;
        for (int idx = tid; idx < NW; idx += 128) {
            int oc = idx % OCT;
            int rem = idx / OCT;
            int k = rem % 9;
            int c = rem / 9;
            int gco = oc0 + oc;
            float v = (gco < Cout) ? w[((size_t)gco * Cin + cc0 + c) * 9 + k] : 0.f;
            sW[c][k][oc] = v;
        }
        __syncthreads();

        #pragma unroll 1
        for (int c = 0; c < CC; c++) {
            // (PY+2) x 4 input patch, pre-packed {v,v}
            u64 rp[PY + 2][4];
            #pragma unroll
            for (int r = 0; r < PY + 2; r++) {
                float2 v0 = *reinterpret_cast<const float2*>(&sIn[c][PY * ty + r][2 * tx]);
                float2 v1 = *reinterpret_cast<const float2*>(&sIn[c][PY * ty + r][2 * tx + 2]);
                rp[r][0] = pk2(v0.x, v0.x);
                rp[r][1] = pk2(v0.y, v0.y);
                rp[r][2] = pk2(v1.x, v1.x);
                rp[r][3] = pk2(v1.y, v1.y);
            }
            #pragma unroll
            for (int o4 = 0; o4 < OCT / 4; o4++) {
                #pragma unroll
                for (int k = 0; k < 9; k++) {
                    ulonglong2 wp = *reinterpret_cast<const ulonglong2*>(&sW[c][k][o4 * 4]);
                    int ky = k / 3, kx = k % 3;
                    #pragma unroll
                    for (int py = 0; py < PY; py++) {
                        #pragma unroll
                        for (int px = 0; px < 2; px++) {
                            int p = py * 2 + px;
                            fma2(acc[p][o4 * 2 + 0], rp[py + ky][px + kx], wp.x);
                            fma2(acc[p][o4 * 2 + 1], rp[py + ky][px + kx], wp.y);
                        }
                    }
                }
            }
        }
        __syncthreads();
    }

    int gx = x0 + 2 * tx;
    #pragma unroll
    for (int j = 0; j < NJ; j++) {
        #pragma unroll
        for (int sub = 0; sub < 2; sub++) {
            int gco = oc0 + 2 * j + sub;
            if (gco >= Cout) continue;
            float bb = b[gco];
            #pragma unroll
            for (int py = 0; py < PY; py++) {
                float2 a0 = up2(acc[py * 2 + 0][j]);
                float2 a1 = up2(acc[py * 2 + 1][j]);
                float e0 = (sub ? a0.y : a0.x) + bb;
                float e1 = (sub ? a1.y : a1.x) + bb;
                int gy = y0 + PY * ty + py;
                *reinterpret_cast<float2*>(&out[(size_t)gco * HW + (size_t)gy * W + gx]) =
                    make_float2(e0, e1);
            }
        }
    }
}

// ---------------------------------------------------------------------------
// PAC kernel map: kk4[y][x][t]; channel-parallel with smem reduction.
// Invalid/boundary terms stored as 0 so the apply kernel is branch-free.
// ---------------------------------------------------------------------------
__global__ __launch_bounds__(256) void kk_kernel(
    const float* __restrict__ g, float* __restrict__ kk4,
    int Cg, int Ho, int Wo)
{
    int tx = threadIdx.x;        // 0..31 (pixel)
    int grp = threadIdx.y;       // 0..7  (channel group)
    int xo = blockIdx.x * 32 + tx;
    int y = blockIdx.y;
    int HW = Ho * Wo;
    bool yodd = (y & 1), xodd = (xo & 1);
    int i0 = yodd ? 0 : 1, i1 = yodd ? 2 : 1;
    int j0 = xodd ? 0 : 1, j1 = xodd ? 2 : 1;
    bool vi1 = yodd && (y < Ho - 1);
    bool vj1 = xodd && (xo < Wo - 1);

    int Ya[2] = { y + i0 - 1, y + i1 - 1 };
    int Xb[2] = { xo + j0 - 1, xo + j1 - 1 };
    bool ib[4];
    int off[4];
    #pragma unroll
    for (int a = 0; a < 2; a++)
        #pragma unroll
        for (int bb = 0; bb < 2; bb++) {
            int t = a * 2 + bb;
            ib[t] = (Ya[a] >= 0 && Ya[a] < Ho && Xb[bb] >= 0 && Xb[bb] < Wo);
            off[t] = Ya[a] * Wo + Xb[bb];
        }
    int base = y * Wo + xo;
    float s0 = 0.f, s1 = 0.f, s2 = 0.f, s3 = 0.f;
    for (int c = grp; c < Cg; c += 8) {
        const float* gc = g + (size_t)c * HW;
        float gv = gc[base];
        float n0 = ib[0] ? gc[off[0]] : 0.f;
        float n1 = ib[1] ? gc[off[1]] : 0.f;
        float n2 = ib[2] ? gc[off[2]] : 0.f;
        float n3 = ib[3] ? gc[off[3]] : 0.f;
        float d;
        d = n0 - gv; s0 = fmaf(d, d, s0);
        d = n1 - gv; s1 = fmaf(d, d, s1);
        d = n2 - gv; s2 = fmaf(d, d, s2);
        d = n3 - gv; s3 = fmaf(d, d, s3);
    }
    __shared__ float4 red[8][32];
    red[grp][tx] = make_float4(s0, s1, s2, s3);
    __syncthreads();
    if (grp == 0) {
        s0 = 0.f; s1 = 0.f; s2 = 0.f; s3 = 0.f;
        #pragma unroll
        for (int gidx = 0; gidx < 8; gidx++) {
            float4 v = red[gidx][tx];
            s0 += v.x; s1 += v.y; s2 += v.z; s3 += v.w;
        }
        float4 r;
        r.x = expf(-0.5f * s0);
        r.y = vj1 ? expf(-0.5f * s1) : 0.f;
        r.z = vi1 ? expf(-0.5f * s2) : 0.f;
        r.w = (vi1 && vj1) ? expf(-0.5f * s3) : 0.f;
        reinterpret_cast<float4*>(kk4)[base] = r;
    }
}

// ---------------------------------------------------------------------------
// PAC transposed conv apply — quad-parity, packed f32x2 over oc pairs.
// Each thread computes a 2x2 output quad; 9 weight taps used exactly once:
//   o00: tap(1,1)·in00
//   o01: tap(1,0)·in00 + tap(1,2)·in01
//   o10: tap(0,1)·in00 + tap(2,1)·in10
//   o11: tap(0,0)·in00 + tap(0,2)·in01 + tap(2,0)·in10 + tap(2,2)·in11
// Block = 128 threads (16x8 quads) -> output tile 32x16. Weights (Ci,Co,3,3).
// ---------------------------------------------------------------------------
template <int CC, int OCT>
__global__ __launch_bounds__(128) void pac_kernel(
    const float* __restrict__ x, const float* __restrict__ kk4,
    const float* __restrict__ w, const float* __restrict__ b,
    float* __restrict__ out, int Ci, int Co, int Hin, int Ho)
{
    const int Wo = Ho;
    const int Win = Hin;
    constexpr int QX = 16, QY = 8;
    constexpr int XH = QY + 1, XW = QX + 2;
    constexpr int NJ = OCT / 2;
    __shared__ float sX[CC][XH][XW];
    __shared__ __align__(16) float sW[CC][9][OCT];

    int tx = threadIdx.x, ty = threadIdx.y; // (16, 8)
    int tid = ty * 16 + tx;
    int qx0 = blockIdx.x * QX, qy0 = blockIdx.y * QY;
    int oc0 = blockIdx.z * OCT;
    int ox0 = 2 * (qx0 + tx), oy0 = 2 * (qy0 + ty);
    int HWin = Hin * Win;

    const float4* kp = reinterpret_cast<const float4*>(kk4);
    float4 kq00 = kp[(size_t)oy0 * Wo + ox0];
    float4 kq01 = kp[(size_t)oy0 * Wo + ox0 + 1];
    float4 kq10 = kp[(size_t)(oy0 + 1) * Wo + ox0];
    float4 kq11 = kp[(size_t)(oy0 + 1) * Wo + ox0 + 1];
    float k11 = kq00.x;
    float k10 = kq01.x, k12 = kq01.y;
    float k01 = kq10.x, k21 = kq10.z;
    float k00 = kq11.x, k02 = kq11.y, k20 = kq11.z, k22 = kq11.w;

    u64 acc[4][NJ];  // [0]=o00 [1]=o01 [2]=o10 [3]=o11
    #pragma unroll
    for (int p = 0; p < 4; p++)
        #pragma unroll
        for (int j = 0; j < NJ; j++) acc[p][j] = 0ull;

    // tap t -> destination output pixel
    constexpr int row_of[9] = { 3, 2, 3, 1, 0, 1, 3, 2, 3 };

    for (int cc0 = 0; cc0 < Ci; cc0 += CC) {
        const int NX = CC * XH * XW;
        for (int idx = tid; idx < NX; idx += 128) {
            int c = idx / (XH * XW);
            int r = idx % (XH * XW);
            int ih = r / XW, iw = r % XW;
            int gh = qy0 + ih, gw = qx0 + iw;
            float v = 0.f;
            if (gh < Hin && gw < Win)
                v = x[(size_t)(cc0 + c) * HWin + (size_t)gh * Win + gw];
            sX[c][ih][iw] = v;
        }
        const int NW = CC * 9 * OCT;
        for (int idx = tid; idx < NW; idx += 128) {
            int oc = idx % OCT;
            int rem = idx / OCT;
            int tap = rem % 9;
            int c = rem / 9;
            int gco = oc0 + oc;
            float v = (gco < Co) ? w[((size_t)(cc0 + c) * Co + gco) * 9 + tap] : 0.f;
            sW[c][tap][oc] = v;
        }
        __syncthreads();

        #pragma unroll 1
        for (int c = 0; c < CC; c++) {
            float in00 = sX[c][ty][tx],     in01 = sX[c][ty][tx + 1];
            float in10 = sX[c][ty + 1][tx], in11 = sX[c][ty + 1][tx + 1];
            float pv[9];
            pv[0] = k00 * in00;
            pv[1] = k01 * in00;
            pv[2] = k02 * in01;
            pv[3] = k10 * in00;
            pv[4] = k11 * in00;
            pv[5] = k12 * in01;
            pv[6] = k20 * in10;
            pv[7] = k21 * in10;
            pv[8] = k22 * in11;
            u64 pp[9];
            #pragma unroll
            for (int t = 0; t < 9; t++) pp[t] = pk2(pv[t], pv[t]);
            #pragma unroll
            for (int o4 = 0; o4 < OCT / 4; o4++) {
                #pragma unroll
                for (int t = 0; t < 9; t++) {
                    ulonglong2 wp = *reinterpret_cast<const ulonglong2*>(&sW[c][t][o4 * 4]);
                    int p = row_of[t];
                    fma2(acc[p][o4 * 2 + 0], pp[t], wp.x);
                    fma2(acc[p][o4 * 2 + 1], pp[t], wp.y);
                }
            }
        }
        __syncthreads();
    }

    size_t HWo = (size_t)Ho * Wo;
    #pragma unroll
    for (int j = 0; j < NJ; j++) {
        #pragma unroll
        for (int sub = 0; sub < 2; sub++) {
            int gco = oc0 + 2 * j + sub;
            if (gco >= Co) continue;
            float bb = b[gco];
            float2 a0 = up2(acc[0][j]);
            float2 a1 = up2(acc[1][j]);
            float2 a2 = up2(acc[2][j]);
            float2 a3 = up2(acc[3][j]);
            float o00 = (sub ? a0.y : a0.x) + bb;
            float o01 = (sub ? a1.y : a1.x) + bb;
            float o10 = (sub ? a2.y : a2.x) + bb;
            float o11 = (sub ? a3.y : a3.x) + bb;
            *reinterpret_cast<float2*>(&out[(size_t)gco * HWo + (size_t)oy0 * Wo + ox0]) =
                make_float2(o00, o01);
            *reinterpret_cast<float2*>(&out[(size_t)gco * HWo + (size_t)(oy0 + 1) * Wo + ox0]) =
                make_float2(o10, o11);
        }
    }
}

// ---------------------------------------------------------------------------
// Launcher
// ---------------------------------------------------------------------------
extern "C" void kernel_launch(void* const* d_in, const int* in_sizes, int n_in,
                              void* d_out, int out_size)
{
    (void)in_sizes; (void)n_in; (void)out_size;
    const float* x      = (const float*)d_in[0];
    const float* ef2    = (const float*)d_in[1];
    const float* ef1    = (const float*)d_in[2];
    const float* w_adj2 = (const float*)d_in[3];
    const float* b_adj2 = (const float*)d_in[4];
    const float* w_adj1 = (const float*)d_in[5];
    const float* b_adj1 = (const float*)d_in[6];
    const float* w_p16  = (const float*)d_in[7];
    const float* b_p16  = (const float*)d_in[8];
    const float* w_p20  = (const float*)d_in[9];
    const float* b_p20  = (const float*)d_in[10];
    const float* w_o    = (const float*)d_in[11];
    const float* b_o    = (const float*)d_in[12];
    float* out = (float*)d_out;

    float *px0, *pg2, *pk16, *px1, *pg1, *pk20, *px2;
    cudaGetSymbolAddress((void**)&px0, g_x0);
    cudaGetSymbolAddress((void**)&pg2, g_g2);
    cudaGetSymbolAddress((void**)&pk16, g_kk16);
    cudaGetSymbolAddress((void**)&px1, g_x1);
    cudaGetSymbolAddress((void**)&pg1, g_g1);
    cudaGetSymbolAddress((void**)&pk20, g_kk20);
    cudaGetSymbolAddress((void**)&px2, g_x2);

    dim3 blk(16, 8);
    dim3 kblk(32, 8);

    // x = double inorm+residual (fused analytically)
    inorm2_kernel<<<256, 256>>>(x, px0, 64 * 64);

    // g2 = conv3x3(ef_lv2): 128 -> 256 @ 128x128
    conv3x3_kernel<8, 8, 2><<<dim3(4, 8, 32), blk>>>(ef2, w_adj2, b_adj2, pg2, 128, 256, 128, 128);

    // kk for pac16 (guide channels = 256, Ho = 128)
    kk_kernel<<<dim3(4, 128), kblk>>>(pg2, pk16, 256, 128, 128);

    // pac16: 256 -> 128, out 128x128  (OCT=4 -> grid z=32 for occupancy)
    pac_kernel<16, 4><<<dim3(4, 8, 32), blk>>>(px0, pk16, w_p16, b_p16, px1, 256, 128, 64, 128);

    // double inorm+res (in place)
    inorm2_kernel<<<128, 256>>>(px1, px1, 128 * 128);

    // g1 = conv3x3(ef_lv1): 64 -> 128 @ 256x256
    conv3x3_kernel<8, 8, 2><<<dim3(8, 16, 16), blk>>>(ef1, w_adj1, b_adj1, pg1, 64, 128, 256, 256);

    // kk for pac20 (guide channels = 128, Ho = 256)
    kk_kernel<<<dim3(8, 256), kblk>>>(pg1, pk20, 128, 256, 256);

    // pac20: 128 -> 64, out 256x256  (OCT=4 -> grid z=16)
    pac_kernel<16, 4><<<dim3(8, 16, 16), blk>>>(px1, pk20, w_p20, b_p20, px2, 128, 64, 128, 256);

    // double inorm+res (in place)
    inorm2_kernel<<<64, 256>>>(px2, px2, 256 * 256);

    // final conv: 64 -> 3 @ 256x256 straight into d_out (PY=1 -> 256 blocks)
    conv3x3_kernel<8, 4, 1><<<dim3(8, 32, 1), blk>>>(px2, w_o, b_o, out, 64, 3, 256, 256);
}